// round 5
// baseline (speedup 1.0000x reference)
#include <cuda_runtime.h>
#include <cuda_fp16.h>
#include <cstdint>

#define N_ROWS 8192
#define FFN    4096
#define EMB    1024

#define BM 128
#define BN 128
#define BK 32
#define LDS (BK + 8)      // 40 halves per row: conflict-free ldmatrix
#define KT  (FFN / BK)    // 128 k-tiles

// Static scratch (allocation-free rule)
__device__ __align__(16) __half g_h[(size_t)N_ROWS * FFN];   // gelu(x)*mask*scale, fp16
__device__ __align__(16) __half g_w[(size_t)EMB * FFN];      // weight as fp16
__device__ __align__(16) __half g_bias[EMB];
__device__ int g_swap;   // 0: bigA=x,bigB=mask ; 1: swapped
__device__ int g_f32;    // 1: fp32 x / int32 mask / fp32 out ; 0: fp16 x / byte mask / fp16 out

// ---------------------------------------------------------------------------
// Sniff: classify the two 33.5M-element buffers and the dtype scenario.
// int32 mask: every word <= 1. byte mask: every byte <= 1. Gaussian data: neither.
// ---------------------------------------------------------------------------
__global__ void sniff_k(const unsigned* __restrict__ A, const unsigned* __restrict__ B) {
    unsigned a = A[threadIdx.x];
    unsigned b = B[threadIdx.x];
    unsigned wa = __ballot_sync(~0u, a <= 1u);
    unsigned wb = __ballot_sync(~0u, b <= 1u);
    unsigned ba = __ballot_sync(~0u, (a & 0xFEFEFEFEu) == 0u);
    unsigned bb = __ballot_sync(~0u, (b & 0xFEFEFEFEu) == 0u);
    if (threadIdx.x == 0) {
        int sw, f32;
        if      (wb == ~0u) { sw = 0; f32 = 1; }   // B is int32 mask (expected order)
        else if (wa == ~0u) { sw = 1; f32 = 1; }
        else if (bb == ~0u) { sw = 0; f32 = 0; }   // B is byte mask
        else if (ba == ~0u) { sw = 1; f32 = 0; }
        else                { sw = 0; f32 = 1; }   // fallback
        g_swap = sw; g_f32 = f32;
    }
}

// ---------------------------------------------------------------------------
// Pass 1: g_h = fp16( fp32_gelu(x) ) * mask * fp16(1/0.9), 8 elems/thread
// ---------------------------------------------------------------------------
__global__ void __launch_bounds__(256) gelu_mask_k(const void* __restrict__ A,
                                                   const void* __restrict__ B) {
    const int sw = g_swap, f32 = g_f32;
    const char* xp = (const char*)(sw ? B : A);
    const char* mp = (const char*)(sw ? A : B);
    size_t idx = ((size_t)blockIdx.x * 256 + threadIdx.x) * 8;

    float xf[8];
    unsigned char keep[8];
    if (f32) {
        const float4* xv = (const float4*)(xp + idx * 4);
        float4 v0 = xv[0], v1 = xv[1];
        xf[0]=v0.x; xf[1]=v0.y; xf[2]=v0.z; xf[3]=v0.w;
        xf[4]=v1.x; xf[5]=v1.y; xf[6]=v1.z; xf[7]=v1.w;
        const int4* mv = (const int4*)(mp + idx * 4);
        int4 m0 = mv[0], m1 = mv[1];
        keep[0]=(unsigned char)m0.x; keep[1]=(unsigned char)m0.y;
        keep[2]=(unsigned char)m0.z; keep[3]=(unsigned char)m0.w;
        keep[4]=(unsigned char)m1.x; keep[5]=(unsigned char)m1.y;
        keep[6]=(unsigned char)m1.z; keep[7]=(unsigned char)m1.w;
    } else {
        uint4 hv = *(const uint4*)(xp + idx * 2);
        __half hs[8]; *reinterpret_cast<uint4*>(hs) = hv;
#pragma unroll
        for (int i = 0; i < 8; i++) xf[i] = __half2float(hs[i]);
        uint2 mb = *(const uint2*)(mp + idx);
        *reinterpret_cast<uint2*>(keep) = mb;
    }

    const __half sc = __float2half(1.0f / 0.9f);
    __half hs[8];
#pragma unroll
    for (int i = 0; i < 8; i++) {
        float g  = 0.5f * xf[i] * (1.0f + erff(xf[i] * 0.70710678118654752440f));
        __half gh = __float2half(g);
        hs[i] = keep[i] ? __hmul(gh, sc) : __ushort_as_half((unsigned short)0);
    }
    *reinterpret_cast<uint4*>(g_h + idx) = *reinterpret_cast<uint4*>(hs);
}

// ---------------------------------------------------------------------------
// Weight / bias -> fp16 scratch
// ---------------------------------------------------------------------------
__global__ void __launch_bounds__(256) wconv_k(const void* __restrict__ w) {
    size_t i = ((size_t)blockIdx.x * 256 + threadIdx.x) * 4;
    if (g_f32) {
        float4 v = *(const float4*)((const float*)w + i);
        __half h[4] = {__float2half(v.x), __float2half(v.y),
                       __float2half(v.z), __float2half(v.w)};
        *reinterpret_cast<uint2*>(g_w + i) = *reinterpret_cast<uint2*>(h);
    } else {
        *reinterpret_cast<uint2*>(g_w + i) = *(const uint2*)((const __half*)w + i);
    }
}

__global__ void biasconv_k(const void* __restrict__ b) {
    int i = threadIdx.x * 4;
    if (i < EMB) {
        if (g_f32) {
            float4 v = *(const float4*)((const float*)b + i);
            __half h[4] = {__float2half(v.x), __float2half(v.y),
                           __float2half(v.z), __float2half(v.w)};
            *reinterpret_cast<uint2*>(g_bias + i) = *reinterpret_cast<uint2*>(h);
        } else {
            *reinterpret_cast<uint2*>(g_bias + i) = *(const uint2*)((const __half*)b + i);
        }
    }
}

// ---------------------------------------------------------------------------
// Pass 2: y = g_h @ g_w^T + bias   (M=8192, N=1024, K=4096)
// 8 warps (2x4), warp tile 64x32, mma.sync m16n8k16 f32-accum, cp.async pipe.
// ---------------------------------------------------------------------------
__global__ void __launch_bounds__(256) gemm_k(void* __restrict__ outv) {
    __shared__ __half As[2][BM * LDS];
    __shared__ __half Bs[2][BN * LDS];

    const int f32o = g_f32;
    const int tid  = threadIdx.x;
    const int lane = tid & 31;
    const int warp = tid >> 5;
    const int wm   = (warp >> 2) * 64;
    const int wn   = (warp & 3) * 32;

    const int mBase = blockIdx.y * BM;
    const int nBase = blockIdx.x * BN;

    const __half* Aglob = g_h + (size_t)mBase * FFN;
    const __half* Bglob = g_w + (size_t)nBase * FFN;

    float acc[4][4][4];
#pragma unroll
    for (int a = 0; a < 4; a++)
#pragma unroll
        for (int b = 0; b < 4; b++)
#pragma unroll
            for (int c = 0; c < 4; c++) acc[a][b][c] = 0.f;

    auto loadTile = [&](int kt, int buf) {
#pragma unroll
        for (int i = 0; i < 2; i++) {
            int idx = tid + i * 256;
            int row = idx >> 2;
            int col = (idx & 3) * 8;
            uint32_t sA = (uint32_t)__cvta_generic_to_shared(&As[buf][row * LDS + col]);
            const __half* gA = Aglob + (size_t)row * FFN + kt * BK + col;
            asm volatile("cp.async.cg.shared.global [%0], [%1], 16;\n" :: "r"(sA), "l"(gA));
            uint32_t sB = (uint32_t)__cvta_generic_to_shared(&Bs[buf][row * LDS + col]);
            const __half* gB = Bglob + (size_t)row * FFN + kt * BK + col;
            asm volatile("cp.async.cg.shared.global [%0], [%1], 16;\n" :: "r"(sB), "l"(gB));
        }
    };

    loadTile(0, 0);
    asm volatile("cp.async.commit_group;\n");

    int buf = 0;
    for (int kt = 0; kt < KT; ++kt) {
        if (kt + 1 < KT) {
            loadTile(kt + 1, buf ^ 1);
            asm volatile("cp.async.commit_group;\n");
            asm volatile("cp.async.wait_group 1;\n");
        } else {
            asm volatile("cp.async.wait_group 0;\n");
        }
        __syncthreads();

#pragma unroll
        for (int ks = 0; ks < 2; ks++) {
            uint32_t a[4][4];
#pragma unroll
            for (int mi = 0; mi < 4; mi++) {
                int r = wm + mi * 16 + ((lane >> 3) & 1) * 8 + (lane & 7);
                int c = ks * 16 + (lane >> 4) * 8;
                uint32_t addr = (uint32_t)__cvta_generic_to_shared(&As[buf][r * LDS + c]);
                asm volatile("ldmatrix.sync.aligned.m8n8.x4.shared.b16 {%0,%1,%2,%3}, [%4];\n"
                             : "=r"(a[mi][0]), "=r"(a[mi][1]), "=r"(a[mi][2]), "=r"(a[mi][3])
                             : "r"(addr));
            }
            uint32_t b[4][2];
#pragma unroll
            for (int nj = 0; nj < 2; nj++) {
                int r = wn + nj * 16 + (lane >> 4) * 8 + (lane & 7);
                int c = ks * 16 + ((lane >> 3) & 1) * 8;
                uint32_t addr = (uint32_t)__cvta_generic_to_shared(&Bs[buf][r * LDS + c]);
                asm volatile("ldmatrix.sync.aligned.m8n8.x4.shared.b16 {%0,%1,%2,%3}, [%4];\n"
                             : "=r"(b[2 * nj][0]), "=r"(b[2 * nj][1]),
                               "=r"(b[2 * nj + 1][0]), "=r"(b[2 * nj + 1][1])
                             : "r"(addr));
            }
#pragma unroll
            for (int mi = 0; mi < 4; mi++)
#pragma unroll
                for (int ni = 0; ni < 4; ni++) {
                    asm volatile(
                        "mma.sync.aligned.m16n8k16.row.col.f32.f16.f16.f32 "
                        "{%0,%1,%2,%3}, {%4,%5,%6,%7}, {%8,%9}, {%0,%1,%2,%3};\n"
                        : "+f"(acc[mi][ni][0]), "+f"(acc[mi][ni][1]),
                          "+f"(acc[mi][ni][2]), "+f"(acc[mi][ni][3])
                        : "r"(a[mi][0]), "r"(a[mi][1]), "r"(a[mi][2]), "r"(a[mi][3]),
                          "r"(b[ni][0]), "r"(b[ni][1]));
                }
        }
        buf ^= 1;
        __syncthreads();
    }

    // Epilogue: fp16(acc) + fp16 bias, then store per __output__ dtype
#pragma unroll
    for (int mi = 0; mi < 4; mi++) {
#pragma unroll
        for (int ni = 0; ni < 4; ni++) {
            int row = mBase + wm + mi * 16 + (lane >> 2);
            int col = nBase + wn + ni * 8 + (lane & 3) * 2;
            __half2 b2 = *reinterpret_cast<const __half2*>(g_bias + col);
            __half2 v0 = __halves2half2(__float2half(acc[mi][ni][0]),
                                        __float2half(acc[mi][ni][1]));
            v0 = __hadd2(v0, b2);
            __half2 v1 = __halves2half2(__float2half(acc[mi][ni][2]),
                                        __float2half(acc[mi][ni][3]));
            v1 = __hadd2(v1, b2);
            if (f32o) {
                float* out = (float*)outv;
                *reinterpret_cast<float2*>(out + (size_t)row * EMB + col) =
                    make_float2(__low2float(v0), __high2float(v0));
                *reinterpret_cast<float2*>(out + (size_t)(row + 8) * EMB + col) =
                    make_float2(__low2float(v1), __high2float(v1));
            } else {
                __half* out = (__half*)outv;
                *reinterpret_cast<__half2*>(out + (size_t)row * EMB + col) = v0;
                *reinterpret_cast<__half2*>(out + (size_t)(row + 8) * EMB + col) = v1;
            }
        }
    }
}

// ---------------------------------------------------------------------------
extern "C" void kernel_launch(void* const* d_in, const int* in_sizes, int n_in,
                              void* d_out, int out_size) {
    const void* bigA = nullptr;
    const void* bigB = nullptr;
    const void* w    = nullptr;
    const void* bias = nullptr;
    for (int i = 0; i < n_in; i++) {
        if (in_sizes[i] == EMB)                 bias = d_in[i];
        else if (in_sizes[i] == EMB * FFN)      w    = d_in[i];
        else if (!bigA)                         bigA = d_in[i];
        else                                    bigB = d_in[i];
    }

    sniff_k<<<1, 32>>>((const unsigned*)bigA, (const unsigned*)bigB);
    gelu_mask_k<<<((size_t)N_ROWS * FFN) / (256 * 8), 256>>>(bigA, bigB);
    wconv_k<<<(EMB * FFN) / (256 * 4), 256>>>(w);
    biasconv_k<<<1, 256>>>(bias);

    dim3 grid(EMB / BN, N_ROWS / BM);
    gemm_k<<<grid, 256>>>(d_out);
}

// round 7
// speedup vs baseline: 1.2945x; 1.2945x over previous
#include <cuda_runtime.h>
#include <cuda_fp16.h>
#include <cstdint>

#define N_ROWS 8192
#define FFN    4096
#define EMB    1024

// ---------------- HMMA GEMM config ----------------
#define BM 128
#define BN 256
#define BK 64
#define STAGES 3
#define KITERS (FFN / BK)                       // 64
#define A_STAGE_BYTES (BM * BK * 2)             // 16 KB (128B rows, SW128)
#define B_STAGE_BYTES (BN * BK * 2)             // 32 KB
#define STAGE_BYTES (A_STAGE_BYTES + B_STAGE_BYTES)   // 48 KB
#define SMEM_TOTAL (STAGES * STAGE_BYTES)       // 147456 B

// Static scratch (allocation-free rule)
__device__ __align__(16) __half g_h[(size_t)N_ROWS * FFN];   // gelu(x)*mask*scale
__device__ __align__(16) __half g_w[(size_t)EMB * FFN];      // weight fp16
__device__ __align__(16) __half g_bias[EMB];
__device__ int g_swap;
__device__ int g_f32;

// ---------------------------------------------------------------------------
// Sniff: classify buffer order + dtype scenario (verified in R5)
// ---------------------------------------------------------------------------
__global__ void sniff_k(const unsigned* __restrict__ A, const unsigned* __restrict__ B) {
    unsigned a = A[threadIdx.x];
    unsigned b = B[threadIdx.x];
    unsigned wa = __ballot_sync(~0u, a <= 1u);
    unsigned wb = __ballot_sync(~0u, b <= 1u);
    unsigned ba = __ballot_sync(~0u, (a & 0xFEFEFEFEu) == 0u);
    unsigned bb = __ballot_sync(~0u, (b & 0xFEFEFEFEu) == 0u);
    if (threadIdx.x == 0) {
        int sw, f32;
        if      (wb == ~0u) { sw = 0; f32 = 1; }
        else if (wa == ~0u) { sw = 1; f32 = 1; }
        else if (bb == ~0u) { sw = 0; f32 = 0; }
        else if (ba == ~0u) { sw = 1; f32 = 0; }
        else                { sw = 0; f32 = 1; }
        g_swap = sw; g_f32 = f32;
    }
}

// ---------------------------------------------------------------------------
// Pass 1: g_h = fp16( fp32_gelu(x) ) * mask * fp16(1/0.9)
// ---------------------------------------------------------------------------
__global__ void __launch_bounds__(256) gelu_mask_k(const void* __restrict__ A,
                                                   const void* __restrict__ B) {
    const int sw = g_swap, f32 = g_f32;
    const char* xp = (const char*)(sw ? B : A);
    const char* mp = (const char*)(sw ? A : B);
    size_t idx = ((size_t)blockIdx.x * 256 + threadIdx.x) * 8;

    float xf[8];
    unsigned char keep[8];
    if (f32) {
        const float4* xv = (const float4*)(xp + idx * 4);
        float4 v0 = xv[0], v1 = xv[1];
        xf[0]=v0.x; xf[1]=v0.y; xf[2]=v0.z; xf[3]=v0.w;
        xf[4]=v1.x; xf[5]=v1.y; xf[6]=v1.z; xf[7]=v1.w;
        const int4* mv = (const int4*)(mp + idx * 4);
        int4 m0 = mv[0], m1 = mv[1];
        keep[0]=(unsigned char)m0.x; keep[1]=(unsigned char)m0.y;
        keep[2]=(unsigned char)m0.z; keep[3]=(unsigned char)m0.w;
        keep[4]=(unsigned char)m1.x; keep[5]=(unsigned char)m1.y;
        keep[6]=(unsigned char)m1.z; keep[7]=(unsigned char)m1.w;
    } else {
        uint4 hv = *(const uint4*)(xp + idx * 2);
        __half hs[8]; *reinterpret_cast<uint4*>(hs) = hv;
#pragma unroll
        for (int i = 0; i < 8; i++) xf[i] = __half2float(hs[i]);
        uint2 mb = *(const uint2*)(mp + idx);
        *reinterpret_cast<uint2*>(keep) = mb;
    }

    const __half sc = __float2half(1.0f / 0.9f);
    __half hs[8];
#pragma unroll
    for (int i = 0; i < 8; i++) {
        float g  = 0.5f * xf[i] * (1.0f + erff(xf[i] * 0.70710678118654752440f));
        __half gh = __float2half(g);
        hs[i] = keep[i] ? __hmul(gh, sc) : __ushort_as_half((unsigned short)0);
    }
    *reinterpret_cast<uint4*>(g_h + idx) = *reinterpret_cast<uint4*>(hs);
}

// ---------------------------------------------------------------------------
// Weight / bias -> fp16 scratch
// ---------------------------------------------------------------------------
__global__ void __launch_bounds__(256) wconv_k(const void* __restrict__ w) {
    size_t i = ((size_t)blockIdx.x * 256 + threadIdx.x) * 4;
    if (g_f32) {
        float4 v = *(const float4*)((const float*)w + i);
        __half h[4] = {__float2half(v.x), __float2half(v.y),
                       __float2half(v.z), __float2half(v.w)};
        *reinterpret_cast<uint2*>(g_w + i) = *reinterpret_cast<uint2*>(h);
    } else {
        *reinterpret_cast<uint2*>(g_w + i) = *(const uint2*)((const __half*)w + i);
    }
}

__global__ void biasconv_k(const void* __restrict__ b) {
    int i = threadIdx.x * 4;
    if (i < EMB) {
        if (g_f32) {
            float4 v = *(const float4*)((const float*)b + i);
            __half h[4] = {__float2half(v.x), __float2half(v.y),
                           __float2half(v.z), __float2half(v.w)};
            *reinterpret_cast<uint2*>(g_bias + i) = *reinterpret_cast<uint2*>(h);
        } else {
            *reinterpret_cast<uint2*>(g_bias + i) = *(const uint2*)((const __half*)b + i);
        }
    }
}

// ---------------------------------------------------------------------------
// Pass 2: y = g_h @ g_w^T + bias  (M=8192, N=1024, K=4096)
// 512 threads = 16 warps (2x8), warp tile 64x32, mma.sync m16n8k16 f32-accum.
// SW128-swizzled smem, 3-stage cp.async pipeline, BK=64.
// ---------------------------------------------------------------------------
__global__ void __launch_bounds__(512, 1) gemm_k(void* __restrict__ outv) {
    extern __shared__ __align__(1024) char sm[];
    const uint32_t smem_base = (uint32_t)__cvta_generic_to_shared(sm);

    const int f32o = g_f32;
    const int tid  = threadIdx.x;
    const int lane = tid & 31;
    const int warp = tid >> 5;
    const int wm   = (warp >> 3) * 64;   // 2 warp rows
    const int wn   = (warp & 7) * 32;    // 8 warp cols

    const int mBase = blockIdx.y * BM;
    const int nBase = blockIdx.x * BN;

    const __half* Aglob = g_h + (size_t)mBase * FFN;
    const __half* Bglob = g_w + (size_t)nBase * FFN;

    float acc[4][4][4];
#pragma unroll
    for (int a = 0; a < 4; a++)
#pragma unroll
        for (int b = 0; b < 4; b++)
#pragma unroll
            for (int c = 0; c < 4; c++) acc[a][b][c] = 0.f;

    // SW128 swizzle of a byte offset with 128B rows: chunk ^= row%8
    auto swz = [](uint32_t off) -> uint32_t { return off ^ ((off >> 3) & 0x70); };

    auto fill = [&](int kt) {
        int buf = kt % STAGES;
        uint32_t sA = smem_base + buf * STAGE_BYTES;
        uint32_t sB = sA + A_STAGE_BYTES;
        const __half* Ag = Aglob + kt * BK;
        const __half* Bg = Bglob + kt * BK;
#pragma unroll
        for (int i = 0; i < 2; i++) {            // A: 128 rows x 8 x 16B = 1024 chunks
            int idx = tid + (i << 9);
            int row = idx >> 3, c = idx & 7;
            uint32_t off = (uint32_t)(row * 128 + c * 16);
            asm volatile("cp.async.cg.shared.global [%0], [%1], 16;"
                         :: "r"(sA + (off ^ ((off >> 3) & 0x70))),
                            "l"(Ag + (size_t)row * FFN + c * 8));
        }
#pragma unroll
        for (int i = 0; i < 4; i++) {            // B: 256 rows x 8 x 16B = 2048 chunks
            int idx = tid + (i << 9);
            int row = idx >> 3, c = idx & 7;
            uint32_t off = (uint32_t)(row * 128 + c * 16);
            asm volatile("cp.async.cg.shared.global [%0], [%1], 16;"
                         :: "r"(sB + (off ^ ((off >> 3) & 0x70))),
                            "l"(Bg + (size_t)row * FFN + c * 8));
        }
        asm volatile("cp.async.commit_group;");
    };

    fill(0); fill(1);

    for (int kt = 0; kt < KITERS; ++kt) {
        if (kt + 1 < KITERS) asm volatile("cp.async.wait_group 1;");
        else                 asm volatile("cp.async.wait_group 0;");
        __syncthreads();

        int buf = kt % STAGES;
        uint32_t sA = smem_base + buf * STAGE_BYTES;
        uint32_t sB = sA + A_STAGE_BYTES;

#pragma unroll
        for (int ks = 0; ks < 4; ks++) {         // BK=64 -> 4 x k16
            uint32_t a[4][4];
#pragma unroll
            for (int mi = 0; mi < 4; mi++) {
                int r = wm + mi * 16 + ((lane >> 3) & 1) * 8 + (lane & 7);
                int c = ks * 16 + (lane >> 4) * 8;
                uint32_t addr = sA + swz((uint32_t)(r * 128 + c * 2));
                asm volatile("ldmatrix.sync.aligned.m8n8.x4.shared.b16 {%0,%1,%2,%3}, [%4];"
                             : "=r"(a[mi][0]), "=r"(a[mi][1]), "=r"(a[mi][2]), "=r"(a[mi][3])
                             : "r"(addr));
            }
            uint32_t b[4][2];
#pragma unroll
            for (int nj = 0; nj < 2; nj++) {
                int r = wn + nj * 16 + (lane >> 4) * 8 + (lane & 7);
                int c = ks * 16 + ((lane >> 3) & 1) * 8;
                uint32_t addr = sB + swz((uint32_t)(r * 128 + c * 2));
                asm volatile("ldmatrix.sync.aligned.m8n8.x4.shared.b16 {%0,%1,%2,%3}, [%4];"
                             : "=r"(b[2 * nj][0]), "=r"(b[2 * nj][1]),
                               "=r"(b[2 * nj + 1][0]), "=r"(b[2 * nj + 1][1])
                             : "r"(addr));
            }
#pragma unroll
            for (int mi = 0; mi < 4; mi++)
#pragma unroll
                for (int ni = 0; ni < 4; ni++) {
                    asm volatile(
                        "mma.sync.aligned.m16n8k16.row.col.f32.f16.f16.f32 "
                        "{%0,%1,%2,%3}, {%4,%5,%6,%7}, {%8,%9}, {%0,%1,%2,%3};"
                        : "+f"(acc[mi][ni][0]), "+f"(acc[mi][ni][1]),
                          "+f"(acc[mi][ni][2]), "+f"(acc[mi][ni][3])
                        : "r"(a[mi][0]), "r"(a[mi][1]), "r"(a[mi][2]), "r"(a[mi][3]),
                          "r"(b[ni][0]), "r"(b[ni][1]));
                }
        }
        __syncthreads();
        if (kt + 2 < KITERS) fill(kt + 2);
    }

    // Epilogue: fp16(acc) + fp16 bias, store per __output__ dtype
#pragma unroll
    for (int mi = 0; mi < 4; mi++) {
#pragma unroll
        for (int ni = 0; ni < 4; ni++) {
            int row = mBase + wm + mi * 16 + (lane >> 2);
            int col = nBase + wn + ni * 8 + (lane & 3) * 2;
            __half2 b2 = *reinterpret_cast<const __half2*>(g_bias + col);
            __half2 v0 = __halves2half2(__float2half(acc[mi][ni][0]),
                                        __float2half(acc[mi][ni][1]));
            v0 = __hadd2(v0, b2);
            __half2 v1 = __halves2half2(__float2half(acc[mi][ni][2]),
                                        __float2half(acc[mi][ni][3]));
            v1 = __hadd2(v1, b2);
            if (f32o) {
                float* out = (float*)outv;
                *reinterpret_cast<float2*>(out + (size_t)row * EMB + col) =
                    make_float2(__low2float(v0), __high2float(v0));
                *reinterpret_cast<float2*>(out + (size_t)(row + 8) * EMB + col) =
                    make_float2(__low2float(v1), __high2float(v1));
            } else {
                __half* out = (__half*)outv;
                *reinterpret_cast<__half2*>(out + (size_t)row * EMB + col) = v0;
                *reinterpret_cast<__half2*>(out + (size_t)(row + 8) * EMB + col) = v1;
            }
        }
    }
}

// ---------------------------------------------------------------------------
extern "C" void kernel_launch(void* const* d_in, const int* in_sizes, int n_in,
                              void* d_out, int out_size) {
    const void* bigA = nullptr;
    const void* bigB = nullptr;
    const void* w    = nullptr;
    const void* bias = nullptr;
    for (int i = 0; i < n_in; i++) {
        if (in_sizes[i] == EMB)            bias = d_in[i];
        else if (in_sizes[i] == EMB * FFN) w    = d_in[i];
        else if (!bigA)                    bigA = d_in[i];
        else                               bigB = d_in[i];
    }

    sniff_k<<<1, 32>>>((const unsigned*)bigA, (const unsigned*)bigB);
    gelu_mask_k<<<((size_t)N_ROWS * FFN) / (256 * 8), 256>>>(bigA, bigB);
    wconv_k<<<(EMB * FFN) / (256 * 4), 256>>>(w);
    biasconv_k<<<1, 256>>>(bias);

    static int smem_set = 0;
    if (!smem_set) {
        cudaFuncSetAttribute(gemm_k, cudaFuncAttributeMaxDynamicSharedMemorySize, SMEM_TOTAL);
        smem_set = 1;
    }
    dim3 grid(EMB / BN, N_ROWS / BM);   // x = n-tiles (fast) for A reuse in L2
    gemm_k<<<grid, 512, SMEM_TOTAL>>>(d_out);
}

// round 8
// speedup vs baseline: 1.4290x; 1.1039x over previous
#include <cuda_runtime.h>
#include <cuda_fp16.h>
#include <cstdint>

#define N_ROWS 8192
#define FFN    4096
#define EMB    1024

// ---------------- HMMA GEMM config ----------------
#define BM 128
#define BN 256
#define BK 64
#define STAGES 4
#define KITERS (FFN / BK)                       // 64
#define A_STAGE_BYTES (BM * BK * 2)             // 16 KB (128B rows, SW128)
#define B_STAGE_BYTES (BN * BK * 2)             // 32 KB
#define STAGE_BYTES (A_STAGE_BYTES + B_STAGE_BYTES)   // 48 KB
#define SMEM_TOTAL (STAGES * STAGE_BYTES)       // 196608 B

#define GELU_BLOCKS 16384                       // 33.5M / (256*8)
#define WCONV_BLOCKS 4096                       // 4.19M / (256*4)
#define PREP_BLOCKS (GELU_BLOCKS + WCONV_BLOCKS + 1)

// Static scratch (allocation-free rule)
__device__ __align__(16) __half g_h[(size_t)N_ROWS * FFN];   // gelu(x)*mask*scale
__device__ __align__(16) __half g_w[(size_t)EMB * FFN];      // weight fp16
__device__ __align__(16) __half g_bias[EMB];

// ---------------------------------------------------------------------------
// Warp-local sniff: classify buffer order + dtype scenario from 32 words each.
// All warps hit the same two 128B lines -> L2 broadcast, ~free.
// Returns (swap, f32) uniform across the warp.
// ---------------------------------------------------------------------------
__device__ __forceinline__ void sniff(const unsigned* A, const unsigned* B,
                                      int& sw, int& f32) {
    int lane = threadIdx.x & 31;
    unsigned a = __ldg(A + lane);
    unsigned b = __ldg(B + lane);
    unsigned wa = __ballot_sync(~0u, a <= 1u);
    unsigned wb = __ballot_sync(~0u, b <= 1u);
    unsigned ba = __ballot_sync(~0u, (a & 0xFEFEFEFEu) == 0u);
    unsigned bb = __ballot_sync(~0u, (b & 0xFEFEFEFEu) == 0u);
    if      (wb == ~0u) { sw = 0; f32 = 1; }
    else if (wa == ~0u) { sw = 1; f32 = 1; }
    else if (bb == ~0u) { sw = 0; f32 = 0; }
    else if (ba == ~0u) { sw = 1; f32 = 0; }
    else                { sw = 0; f32 = 1; }
}

// ---------------------------------------------------------------------------
// Prep (single launch): gelu+mask -> g_h ; weight -> g_w ; bias -> g_bias
// ---------------------------------------------------------------------------
__global__ void __launch_bounds__(256) prep_k(const void* __restrict__ A,
                                              const void* __restrict__ B,
                                              const void* __restrict__ w,
                                              const void* __restrict__ bias) {
    int sw, f32;
    sniff((const unsigned*)A, (const unsigned*)B, sw, f32);

    unsigned bidx = blockIdx.x;
    if (bidx < GELU_BLOCKS) {
        // ---- gelu * mask * scale, 8 elems/thread ----
        const char* xp = (const char*)(sw ? B : A);
        const char* mp = (const char*)(sw ? A : B);
        size_t idx = ((size_t)bidx * 256 + threadIdx.x) * 8;

        float xf[8];
        unsigned char keep[8];
        if (f32) {
            const float4* xv = (const float4*)(xp + idx * 4);
            float4 v0 = xv[0], v1 = xv[1];
            xf[0]=v0.x; xf[1]=v0.y; xf[2]=v0.z; xf[3]=v0.w;
            xf[4]=v1.x; xf[5]=v1.y; xf[6]=v1.z; xf[7]=v1.w;
            const int4* mv = (const int4*)(mp + idx * 4);
            int4 m0 = mv[0], m1 = mv[1];
            keep[0]=(unsigned char)m0.x; keep[1]=(unsigned char)m0.y;
            keep[2]=(unsigned char)m0.z; keep[3]=(unsigned char)m0.w;
            keep[4]=(unsigned char)m1.x; keep[5]=(unsigned char)m1.y;
            keep[6]=(unsigned char)m1.z; keep[7]=(unsigned char)m1.w;
        } else {
            uint4 hv = *(const uint4*)(xp + idx * 2);
            __half hs[8]; *reinterpret_cast<uint4*>(hs) = hv;
#pragma unroll
            for (int i = 0; i < 8; i++) xf[i] = __half2float(hs[i]);
            uint2 mb = *(const uint2*)(mp + idx);
            *reinterpret_cast<uint2*>(keep) = mb;
        }

        const __half sc = __float2half(1.0f / 0.9f);
        __half hs[8];
#pragma unroll
        for (int i = 0; i < 8; i++) {
            float g  = 0.5f * xf[i] * (1.0f + erff(xf[i] * 0.70710678118654752440f));
            __half gh = __float2half(g);
            hs[i] = keep[i] ? __hmul(gh, sc) : __ushort_as_half((unsigned short)0);
        }
        *reinterpret_cast<uint4*>(g_h + idx) = *reinterpret_cast<uint4*>(hs);
    } else if (bidx < GELU_BLOCKS + WCONV_BLOCKS) {
        // ---- weight -> fp16 ----
        size_t i = ((size_t)(bidx - GELU_BLOCKS) * 256 + threadIdx.x) * 4;
        if (f32) {
            float4 v = *(const float4*)((const float*)w + i);
            __half h[4] = {__float2half(v.x), __float2half(v.y),
                           __float2half(v.z), __float2half(v.w)};
            *reinterpret_cast<uint2*>(g_w + i) = *reinterpret_cast<uint2*>(h);
        } else {
            *reinterpret_cast<uint2*>(g_w + i) = *(const uint2*)((const __half*)w + i);
        }
    } else {
        // ---- bias -> fp16 ----
        int i = threadIdx.x * 4;
        if (i < EMB) {
            if (f32) {
                float4 v = *(const float4*)((const float*)bias + i);
                __half h[4] = {__float2half(v.x), __float2half(v.y),
                               __float2half(v.z), __float2half(v.w)};
                *reinterpret_cast<uint2*>(g_bias + i) = *reinterpret_cast<uint2*>(h);
            } else {
                *reinterpret_cast<uint2*>(g_bias + i) = *(const uint2*)((const __half*)bias + i);
            }
        }
    }
}

// ---------------------------------------------------------------------------
// Pass 2: y = g_h @ g_w^T + bias  (M=8192, N=1024, K=4096)
// 512 threads = 16 warps (2x8), warp tile 64x32, mma.sync m16n8k16 f32-accum.
// SW128-swizzled smem, 4-stage cp.async pipeline, BK=64, 1 sync/iter.
// ---------------------------------------------------------------------------
__global__ void __launch_bounds__(512, 1) gemm_k(void* __restrict__ outv,
                                                 const void* __restrict__ A0,
                                                 const void* __restrict__ B0) {
    extern __shared__ __align__(1024) char sm[];
    const uint32_t smem_base = (uint32_t)__cvta_generic_to_shared(sm);

    int snsw, f32o;
    sniff((const unsigned*)A0, (const unsigned*)B0, snsw, f32o);

    const int tid  = threadIdx.x;
    const int lane = tid & 31;
    const int warp = tid >> 5;
    const int wm   = (warp >> 3) * 64;   // 2 warp rows
    const int wn   = (warp & 7) * 32;    // 8 warp cols

    const int mBase = blockIdx.y * BM;
    const int nBase = blockIdx.x * BN;

    const __half* Aglob = g_h + (size_t)mBase * FFN;
    const __half* Bglob = g_w + (size_t)nBase * FFN;

    float acc[4][4][4];
#pragma unroll
    for (int a = 0; a < 4; a++)
#pragma unroll
        for (int b = 0; b < 4; b++)
#pragma unroll
            for (int c = 0; c < 4; c++) acc[a][b][c] = 0.f;

    auto swz = [](uint32_t off) -> uint32_t { return off ^ ((off >> 3) & 0x70); };

    auto fill = [&](int kt) {
        int buf = kt & (STAGES - 1);
        uint32_t sA = smem_base + buf * STAGE_BYTES;
        uint32_t sB = sA + A_STAGE_BYTES;
        const __half* Ag = Aglob + kt * BK;
        const __half* Bg = Bglob + kt * BK;
#pragma unroll
        for (int i = 0; i < 2; i++) {            // A: 1024 x 16B chunks
            int idx = tid + (i << 9);
            int row = idx >> 3, c = idx & 7;
            uint32_t off = (uint32_t)(row * 128 + c * 16);
            asm volatile("cp.async.cg.shared.global [%0], [%1], 16;"
                         :: "r"(sA + (off ^ ((off >> 3) & 0x70))),
                            "l"(Ag + (size_t)row * FFN + c * 8));
        }
#pragma unroll
        for (int i = 0; i < 4; i++) {            // B: 2048 x 16B chunks
            int idx = tid + (i << 9);
            int row = idx >> 3, c = idx & 7;
            uint32_t off = (uint32_t)(row * 128 + c * 16);
            asm volatile("cp.async.cg.shared.global [%0], [%1], 16;"
                         :: "r"(sB + (off ^ ((off >> 3) & 0x70))),
                            "l"(Bg + (size_t)row * FFN + c * 8));
        }
        asm volatile("cp.async.commit_group;");
    };

    fill(0); fill(1); fill(2);

    for (int kt = 0; kt < KITERS; ++kt) {
        int newer = KITERS - 1 - kt;
        if      (newer >= 2) asm volatile("cp.async.wait_group 2;");
        else if (newer == 1) asm volatile("cp.async.wait_group 1;");
        else                 asm volatile("cp.async.wait_group 0;");
        __syncthreads();   // orders cp.async visibility AND buffer reuse

        int buf = kt & (STAGES - 1);
        uint32_t sA = smem_base + buf * STAGE_BYTES;
        uint32_t sB = sA + A_STAGE_BYTES;

#pragma unroll
        for (int ks = 0; ks < 4; ks++) {         // BK=64 -> 4 x k16
            uint32_t a[4][4];
#pragma unroll
            for (int mi = 0; mi < 4; mi++) {
                int r = wm + mi * 16 + ((lane >> 3) & 1) * 8 + (lane & 7);
                int c = ks * 16 + (lane >> 4) * 8;
                uint32_t addr = sA + swz((uint32_t)(r * 128 + c * 2));
                asm volatile("ldmatrix.sync.aligned.m8n8.x4.shared.b16 {%0,%1,%2,%3}, [%4];"
                             : "=r"(a[mi][0]), "=r"(a[mi][1]), "=r"(a[mi][2]), "=r"(a[mi][3])
                             : "r"(addr));
            }
            uint32_t b[4][2];
#pragma unroll
            for (int nj = 0; nj < 2; nj++) {
                int r = wn + nj * 16 + (lane >> 4) * 8 + (lane & 7);
                int c = ks * 16 + ((lane >> 3) & 1) * 8;
                uint32_t addr = sB + swz((uint32_t)(r * 128 + c * 2));
                asm volatile("ldmatrix.sync.aligned.m8n8.x4.shared.b16 {%0,%1,%2,%3}, [%4];"
                             : "=r"(b[2 * nj][0]), "=r"(b[2 * nj][1]),
                               "=r"(b[2 * nj + 1][0]), "=r"(b[2 * nj + 1][1])
                             : "r"(addr));
            }
#pragma unroll
            for (int mi = 0; mi < 4; mi++)
#pragma unroll
                for (int ni = 0; ni < 4; ni++) {
                    asm volatile(
                        "mma.sync.aligned.m16n8k16.row.col.f32.f16.f16.f32 "
                        "{%0,%1,%2,%3}, {%4,%5,%6,%7}, {%8,%9}, {%0,%1,%2,%3};"
                        : "+f"(acc[mi][ni][0]), "+f"(acc[mi][ni][1]),
                          "+f"(acc[mi][ni][2]), "+f"(acc[mi][ni][3])
                        : "r"(a[mi][0]), "r"(a[mi][1]), "r"(a[mi][2]), "r"(a[mi][3]),
                          "r"(b[ni][0]), "r"(b[ni][1]));
                }
        }
        // No trailing sync: fill(kt+3) writes buf (kt-1)%4, whose readers all
        // passed this iteration's leading __syncthreads already.
        if (kt + STAGES - 1 < KITERS) fill(kt + STAGES - 1);
    }

    // Epilogue: fp16(acc) + fp16 bias, store per __output__ dtype
#pragma unroll
    for (int mi = 0; mi < 4; mi++) {
#pragma unroll
        for (int ni = 0; ni < 4; ni++) {
            int row = mBase + wm + mi * 16 + (lane >> 2);
            int col = nBase + wn + ni * 8 + (lane & 3) * 2;
            __half2 b2 = *reinterpret_cast<const __half2*>(g_bias + col);
            __half2 v0 = __halves2half2(__float2half(acc[mi][ni][0]),
                                        __float2half(acc[mi][ni][1]));
            v0 = __hadd2(v0, b2);
            __half2 v1 = __halves2half2(__float2half(acc[mi][ni][2]),
                                        __float2half(acc[mi][ni][3]));
            v1 = __hadd2(v1, b2);
            if (f32o) {
                float* out = (float*)outv;
                *reinterpret_cast<float2*>(out + (size_t)row * EMB + col) =
                    make_float2(__low2float(v0), __high2float(v0));
                *reinterpret_cast<float2*>(out + (size_t)(row + 8) * EMB + col) =
                    make_float2(__low2float(v1), __high2float(v1));
            } else {
                __half* out = (__half*)outv;
                *reinterpret_cast<__half2*>(out + (size_t)row * EMB + col) = v0;
                *reinterpret_cast<__half2*>(out + (size_t)(row + 8) * EMB + col) = v1;
            }
        }
    }
}

// ---------------------------------------------------------------------------
extern "C" void kernel_launch(void* const* d_in, const int* in_sizes, int n_in,
                              void* d_out, int out_size) {
    const void* bigA = nullptr;
    const void* bigB = nullptr;
    const void* w    = nullptr;
    const void* bias = nullptr;
    for (int i = 0; i < n_in; i++) {
        if (in_sizes[i] == EMB)            bias = d_in[i];
        else if (in_sizes[i] == EMB * FFN) w    = d_in[i];
        else if (!bigA)                    bigA = d_in[i];
        else                               bigB = d_in[i];
    }

    prep_k<<<PREP_BLOCKS, 256>>>(bigA, bigB, w, bias);

    static int smem_set = 0;
    if (!smem_set) {
        cudaFuncSetAttribute(gemm_k, cudaFuncAttributeMaxDynamicSharedMemorySize, SMEM_TOTAL);
        smem_set = 1;
    }
    dim3 grid(EMB / BN, N_ROWS / BM);   // x = n-tiles (fast) for A reuse in L2
    gemm_k<<<grid, 512, SMEM_TOTAL>>>(d_out, bigA, bigB);
}

// round 9
// speedup vs baseline: 1.4497x; 1.0145x over previous
#include <cuda_runtime.h>
#include <cuda_fp16.h>
#include <cstdint>

#define N_ROWS 8192
#define FFN    4096
#define EMB    1024

// ---------------- HMMA GEMM config ----------------
#define BM 128
#define BN 128
#define BK 64
#define STAGES 3
#define KITERS (FFN / BK)                       // 64
#define A_STAGE_BYTES (BM * BK * 2)             // 16 KB (128B rows, SW128)
#define B_STAGE_BYTES (BN * BK * 2)             // 16 KB
#define STAGE_BYTES (A_STAGE_BYTES + B_STAGE_BYTES)   // 32 KB
#define SMEM_TOTAL (STAGES * STAGE_BYTES)       // 98304 B -> 2 CTAs/SM

#define GELU_BLOCKS 16384                       // 33.5M / (256*8)
#define WCONV_BLOCKS 4096                       // 4.19M / (256*4)
#define PREP_BLOCKS (GELU_BLOCKS + WCONV_BLOCKS + 1)

// Static scratch (allocation-free rule)
__device__ __align__(16) __half g_h[(size_t)N_ROWS * FFN];   // gelu(x)*mask*scale
__device__ __align__(16) __half g_w[(size_t)EMB * FFN];      // weight fp16
__device__ __align__(16) __half g_bias[EMB];

// ---------------------------------------------------------------------------
// Warp-local sniff: classify buffer order + dtype scenario from 32 words each.
// ---------------------------------------------------------------------------
__device__ __forceinline__ void sniff(const unsigned* A, const unsigned* B,
                                      int& sw, int& f32) {
    int lane = threadIdx.x & 31;
    unsigned a = __ldg(A + lane);
    unsigned b = __ldg(B + lane);
    unsigned wa = __ballot_sync(~0u, a <= 1u);
    unsigned wb = __ballot_sync(~0u, b <= 1u);
    unsigned ba = __ballot_sync(~0u, (a & 0xFEFEFEFEu) == 0u);
    unsigned bb = __ballot_sync(~0u, (b & 0xFEFEFEFEu) == 0u);
    if      (wb == ~0u) { sw = 0; f32 = 1; }
    else if (wa == ~0u) { sw = 1; f32 = 1; }
    else if (bb == ~0u) { sw = 0; f32 = 0; }
    else if (ba == ~0u) { sw = 1; f32 = 0; }
    else                { sw = 0; f32 = 1; }
}

// ---------------------------------------------------------------------------
// Prep (single launch): gelu+mask -> g_h ; weight -> g_w ; bias -> g_bias
// ---------------------------------------------------------------------------
__global__ void __launch_bounds__(256) prep_k(const void* __restrict__ A,
                                              const void* __restrict__ B,
                                              const void* __restrict__ w,
                                              const void* __restrict__ bias) {
    int sw, f32;
    sniff((const unsigned*)A, (const unsigned*)B, sw, f32);

    unsigned bidx = blockIdx.x;
    if (bidx < GELU_BLOCKS) {
        const char* xp = (const char*)(sw ? B : A);
        const char* mp = (const char*)(sw ? A : B);
        size_t idx = ((size_t)bidx * 256 + threadIdx.x) * 8;

        float xf[8];
        unsigned char keep[8];
        if (f32) {
            const float4* xv = (const float4*)(xp + idx * 4);
            float4 v0 = xv[0], v1 = xv[1];
            xf[0]=v0.x; xf[1]=v0.y; xf[2]=v0.z; xf[3]=v0.w;
            xf[4]=v1.x; xf[5]=v1.y; xf[6]=v1.z; xf[7]=v1.w;
            const int4* mv = (const int4*)(mp + idx * 4);
            int4 m0 = mv[0], m1 = mv[1];
            keep[0]=(unsigned char)m0.x; keep[1]=(unsigned char)m0.y;
            keep[2]=(unsigned char)m0.z; keep[3]=(unsigned char)m0.w;
            keep[4]=(unsigned char)m1.x; keep[5]=(unsigned char)m1.y;
            keep[6]=(unsigned char)m1.z; keep[7]=(unsigned char)m1.w;
        } else {
            uint4 hv = *(const uint4*)(xp + idx * 2);
            __half hs[8]; *reinterpret_cast<uint4*>(hs) = hv;
#pragma unroll
            for (int i = 0; i < 8; i++) xf[i] = __half2float(hs[i]);
            uint2 mb = *(const uint2*)(mp + idx);
            *reinterpret_cast<uint2*>(keep) = mb;
        }

        const __half sc = __float2half(1.0f / 0.9f);
        __half hs[8];
#pragma unroll
        for (int i = 0; i < 8; i++) {
            float g  = 0.5f * xf[i] * (1.0f + erff(xf[i] * 0.70710678118654752440f));
            __half gh = __float2half(g);
            hs[i] = keep[i] ? __hmul(gh, sc) : __ushort_as_half((unsigned short)0);
        }
        *reinterpret_cast<uint4*>(g_h + idx) = *reinterpret_cast<uint4*>(hs);
    } else if (bidx < GELU_BLOCKS + WCONV_BLOCKS) {
        size_t i = ((size_t)(bidx - GELU_BLOCKS) * 256 + threadIdx.x) * 4;
        if (f32) {
            float4 v = *(const float4*)((const float*)w + i);
            __half h[4] = {__float2half(v.x), __float2half(v.y),
                           __float2half(v.z), __float2half(v.w)};
            *reinterpret_cast<uint2*>(g_w + i) = *reinterpret_cast<uint2*>(h);
        } else {
            *reinterpret_cast<uint2*>(g_w + i) = *(const uint2*)((const __half*)w + i);
        }
    } else {
        int i = threadIdx.x * 4;
        if (i < EMB) {
            if (f32) {
                float4 v = *(const float4*)((const float*)bias + i);
                __half h[4] = {__float2half(v.x), __float2half(v.y),
                               __float2half(v.z), __float2half(v.w)};
                *reinterpret_cast<uint2*>(g_bias + i) = *reinterpret_cast<uint2*>(h);
            } else {
                *reinterpret_cast<uint2*>(g_bias + i) = *(const uint2*)((const __half*)bias + i);
            }
        }
    }
}

// ---------------------------------------------------------------------------
// Pass 2: y = g_h @ g_w^T + bias  (M=8192, N=1024, K=4096)
// 256 threads = 8 warps (2x4), warp tile 64x32, mma.sync m16n8k16 f32-accum.
// SW128 smem, 3-stage cp.async pipeline, BK=64, 1 sync/iter, 2 CTAs/SM.
// ---------------------------------------------------------------------------
__global__ void __launch_bounds__(256, 2) gemm_k(void* __restrict__ outv,
                                                 const void* __restrict__ A0,
                                                 const void* __restrict__ B0) {
    extern __shared__ __align__(1024) char sm[];
    const uint32_t smem_base = (uint32_t)__cvta_generic_to_shared(sm);

    int snsw, f32o;
    sniff((const unsigned*)A0, (const unsigned*)B0, snsw, f32o);

    const int tid  = threadIdx.x;
    const int lane = tid & 31;
    const int warp = tid >> 5;
    const int wm   = (warp >> 2) * 64;   // 2 warp rows
    const int wn   = (warp & 3) * 32;    // 4 warp cols

    const int mBase = blockIdx.y * BM;
    const int nBase = blockIdx.x * BN;

    const __half* Aglob = g_h + (size_t)mBase * FFN;
    const __half* Bglob = g_w + (size_t)nBase * FFN;

    float acc[4][4][4];
#pragma unroll
    for (int a = 0; a < 4; a++)
#pragma unroll
        for (int b = 0; b < 4; b++)
#pragma unroll
            for (int c = 0; c < 4; c++) acc[a][b][c] = 0.f;

    auto swz = [](uint32_t off) -> uint32_t { return off ^ ((off >> 3) & 0x70); };

    auto fill = [&](int kt) {
        int buf = kt % STAGES;
        uint32_t sA = smem_base + buf * STAGE_BYTES;
        uint32_t sB = sA + A_STAGE_BYTES;
        const __half* Ag = Aglob + kt * BK;
        const __half* Bg = Bglob + kt * BK;
#pragma unroll
        for (int i = 0; i < 4; i++) {            // A: 1024 x 16B chunks / 256 thr
            int idx = tid + (i << 8);
            int row = idx >> 3, c = idx & 7;
            uint32_t off = (uint32_t)(row * 128 + c * 16);
            asm volatile("cp.async.cg.shared.global [%0], [%1], 16;"
                         :: "r"(sA + (off ^ ((off >> 3) & 0x70))),
                            "l"(Ag + (size_t)row * FFN + c * 8));
        }
#pragma unroll
        for (int i = 0; i < 4; i++) {            // B: 1024 x 16B chunks
            int idx = tid + (i << 8);
            int row = idx >> 3, c = idx & 7;
            uint32_t off = (uint32_t)(row * 128 + c * 16);
            asm volatile("cp.async.cg.shared.global [%0], [%1], 16;"
                         :: "r"(sB + (off ^ ((off >> 3) & 0x70))),
                            "l"(Bg + (size_t)row * FFN + c * 8));
        }
        asm volatile("cp.async.commit_group;");
    };

    fill(0); fill(1);

    for (int kt = 0; kt < KITERS; ++kt) {
        if (kt + 1 < KITERS) asm volatile("cp.async.wait_group 1;");
        else                 asm volatile("cp.async.wait_group 0;");
        __syncthreads();   // orders cp.async visibility; refill target is 2-iters-old

        int buf = kt % STAGES;
        uint32_t sA = smem_base + buf * STAGE_BYTES;
        uint32_t sB = sA + A_STAGE_BYTES;

#pragma unroll
        for (int ks = 0; ks < 4; ks++) {         // BK=64 -> 4 x k16
            uint32_t a[4][4];
#pragma unroll
            for (int mi = 0; mi < 4; mi++) {
                int r = wm + mi * 16 + ((lane >> 3) & 1) * 8 + (lane & 7);
                int c = ks * 16 + (lane >> 4) * 8;
                uint32_t addr = sA + swz((uint32_t)(r * 128 + c * 2));
                asm volatile("ldmatrix.sync.aligned.m8n8.x4.shared.b16 {%0,%1,%2,%3}, [%4];"
                             : "=r"(a[mi][0]), "=r"(a[mi][1]), "=r"(a[mi][2]), "=r"(a[mi][3])
                             : "r"(addr));
            }
            uint32_t b[4][2];
#pragma unroll
            for (int nj = 0; nj < 2; nj++) {
                int r = wn + nj * 16 + (lane >> 4) * 8 + (lane & 7);
                int c = ks * 16 + ((lane >> 3) & 1) * 8;
                uint32_t addr = sB + swz((uint32_t)(r * 128 + c * 2));
                asm volatile("ldmatrix.sync.aligned.m8n8.x4.shared.b16 {%0,%1,%2,%3}, [%4];"
                             : "=r"(b[2 * nj][0]), "=r"(b[2 * nj][1]),
                               "=r"(b[2 * nj + 1][0]), "=r"(b[2 * nj + 1][1])
                             : "r"(addr));
            }
#pragma unroll
            for (int mi = 0; mi < 4; mi++)
#pragma unroll
                for (int ni = 0; ni < 4; ni++) {
                    asm volatile(
                        "mma.sync.aligned.m16n8k16.row.col.f32.f16.f16.f32 "
                        "{%0,%1,%2,%3}, {%4,%5,%6,%7}, {%8,%9}, {%0,%1,%2,%3};"
                        : "+f"(acc[mi][ni][0]), "+f"(acc[mi][ni][1]),
                          "+f"(acc[mi][ni][2]), "+f"(acc[mi][ni][3])
                        : "r"(a[mi][0]), "r"(a[mi][1]), "r"(a[mi][2]), "r"(a[mi][3]),
                          "r"(b[ni][0]), "r"(b[ni][1]));
                }
        }
        if (kt + STAGES - 1 < KITERS) fill(kt + STAGES - 1);
    }

    // Epilogue: fp16(acc) + fp16 bias, store per __output__ dtype
#pragma unroll
    for (int mi = 0; mi < 4; mi++) {
#pragma unroll
        for (int ni = 0; ni < 4; ni++) {
            int row = mBase + wm + mi * 16 + (lane >> 2);
            int col = nBase + wn + ni * 8 + (lane & 3) * 2;
            __half2 b2 = *reinterpret_cast<const __half2*>(g_bias + col);
            __half2 v0 = __halves2half2(__float2half(acc[mi][ni][0]),
                                        __float2half(acc[mi][ni][1]));
            v0 = __hadd2(v0, b2);
            __half2 v1 = __halves2half2(__float2half(acc[mi][ni][2]),
                                        __float2half(acc[mi][ni][3]));
            v1 = __hadd2(v1, b2);
            if (f32o) {
                float* out = (float*)outv;
                *reinterpret_cast<float2*>(out + (size_t)row * EMB + col) =
                    make_float2(__low2float(v0), __high2float(v0));
                *reinterpret_cast<float2*>(out + (size_t)(row + 8) * EMB + col) =
                    make_float2(__low2float(v1), __high2float(v1));
            } else {
                __half* out = (__half*)outv;
                *reinterpret_cast<__half2*>(out + (size_t)row * EMB + col) = v0;
                *reinterpret_cast<__half2*>(out + (size_t)(row + 8) * EMB + col) = v1;
            }
        }
    }
}

// ---------------------------------------------------------------------------
extern "C" void kernel_launch(void* const* d_in, const int* in_sizes, int n_in,
                              void* d_out, int out_size) {
    const void* bigA = nullptr;
    const void* bigB = nullptr;
    const void* w    = nullptr;
    const void* bias = nullptr;
    for (int i = 0; i < n_in; i++) {
        if (in_sizes[i] == EMB)            bias = d_in[i];
        else if (in_sizes[i] == EMB * FFN) w    = d_in[i];
        else if (!bigA)                    bigA = d_in[i];
        else                               bigB = d_in[i];
    }

    prep_k<<<PREP_BLOCKS, 256>>>(bigA, bigB, w, bias);

    static int smem_set = 0;
    if (!smem_set) {
        cudaFuncSetAttribute(gemm_k, cudaFuncAttributeMaxDynamicSharedMemorySize, SMEM_TOTAL);
        smem_set = 1;
    }
    dim3 grid(EMB / BN, N_ROWS / BM);   // x = n-tiles (fast) for A reuse in L2
    gemm_k<<<grid, 256, SMEM_TOTAL>>>(d_out, bigA, bigB);
}